// round 14
// baseline (speedup 1.0000x reference)
#include <cuda_runtime.h>
#include <math_constants.h>

#define BB 256
#define DD 768
#define SPLITG 4
#define SPLITL 12
#define GRID 640

// ---- scratch (static device globals; no allocation) ----
__device__ float d_vq[BB * DD];
__device__ float d_tlm[BB * DD];
__device__ float d_simP[BB][2][512];
__device__ float d_Gp[SPLITG][BB * BB];
__device__ float d_GTp[SPLITG][BB * BB];
__device__ float d_Lp[SPLITL][BB * BB];
__device__ float d_lse[3 * BB];
__device__ float d_diagG[BB];
__device__ float d_diagL[BB];
__device__ volatile unsigned int d_bar1 = 0;   // phase A -> B
__device__ volatile unsigned int d_bar2 = 0;   // phase B -> C
__device__ volatile unsigned int d_bar3 = 0;   // phase C -> D
__device__ unsigned int d_ctr = 0;             // phase D completion

__device__ __forceinline__ float sel4(float4 v, int e) {
    return e == 0 ? v.x : e == 1 ? v.y : e == 2 ? v.z : v.w;
}

// Grid barriers. Residency guaranteed: __launch_bounds__(128,5) caps regs so
// 5 blocks/SM x 148 = 740 >= 640 grid blocks -> single co-resident wave.
__device__ __forceinline__ void bar_arrive(volatile unsigned int* bar) {
    __threadfence();
    __syncthreads();
    if (threadIdx.x == 0) atomicAdd((unsigned int*)bar, 1u);
}
__device__ __forceinline__ void bar_wait(volatile unsigned int* bar, unsigned int target) {
    if (threadIdx.x == 0) {
        while (*bar < target) __nanosleep(64);
    }
    __syncthreads();
    __threadfence();
}

// ---- shared-memory views (static union, ~36KB) ----
struct K1Sm {
    float As[4][16 * 33];   // per warp: 16 t-rows x 32 k, pitch 33
    float Bs[4][32 * 33];   // per warp: 32 s-rows x 32 k, pitch 33
    float simb[4][512];
    float sims[512];
    float redm[16];
    float tw[16];
};
struct GemmSm {
    float As[32 * 33];      // A tile: 32 rows x 32 k, pitch 33
    float Bs[64 * 33];      // B tile: 64 rows x 32 k, pitch 33
};
union SmU { K1Sm k1; GemmSm g; };

// ============================================================================
// GEMM body (proven, pipelined): C = A @ B^T on a 32x64 tile, K-slice
// [kbase, kbase+32*nch). 128 threads; thread (tr=tid>>4, tc=tid&15) owns rows
// {tr+8i}, cols {tc+16j}. Pitch-33 conflict-free smem.
// ============================================================================
__device__ __forceinline__ void gemm_body(GemmSm& s, const float* __restrict__ A,
                                          const float* __restrict__ Bm,
                                          float* __restrict__ C, float* __restrict__ CT,
                                          int row0, int col0, int kbase, int nch) {
    int tid = threadIdx.x;
    int tr = tid >> 4, tc = tid & 15;
    float acc[4][4] = {};
    float4 va[2], vb[4];

#pragma unroll
    for (int j = 0; j < 2; j++) {
        int idx = tid + 128 * j, row = idx >> 3, kq = idx & 7;
        va[j] = *(const float4*)(A + (size_t)(row0 + row) * DD + kbase + 4 * kq);
    }
#pragma unroll
    for (int j = 0; j < 4; j++) {
        int idx = tid + 128 * j, row = idx >> 3, kq = idx & 7;
        vb[j] = *(const float4*)(Bm + (size_t)(col0 + row) * DD + kbase + 4 * kq);
    }

    for (int ch = 0; ch < nch; ch++) {
        __syncthreads();
#pragma unroll
        for (int j = 0; j < 2; j++) {
            int idx = tid + 128 * j, row = idx >> 3, kq = idx & 7;
            float* p = &s.As[row * 33 + 4 * kq];
            p[0] = va[j].x; p[1] = va[j].y; p[2] = va[j].z; p[3] = va[j].w;
        }
#pragma unroll
        for (int j = 0; j < 4; j++) {
            int idx = tid + 128 * j, row = idx >> 3, kq = idx & 7;
            float* p = &s.Bs[row * 33 + 4 * kq];
            p[0] = vb[j].x; p[1] = vb[j].y; p[2] = vb[j].z; p[3] = vb[j].w;
        }
        __syncthreads();
        if (ch + 1 < nch) {   // prefetch next chunk (hidden by compute below)
            int kb = kbase + (ch + 1) * 32;
#pragma unroll
            for (int j = 0; j < 2; j++) {
                int idx = tid + 128 * j, row = idx >> 3, kq = idx & 7;
                va[j] = *(const float4*)(A + (size_t)(row0 + row) * DD + kb + 4 * kq);
            }
#pragma unroll
            for (int j = 0; j < 4; j++) {
                int idx = tid + 128 * j, row = idx >> 3, kq = idx & 7;
                vb[j] = *(const float4*)(Bm + (size_t)(col0 + row) * DD + kb + 4 * kq);
            }
        }
#pragma unroll 16
        for (int k = 0; k < 32; k++) {
            float a0 = s.As[(tr)*33 + k];
            float a1 = s.As[(tr + 8) * 33 + k];
            float a2 = s.As[(tr + 16) * 33 + k];
            float a3 = s.As[(tr + 24) * 33 + k];
            float b0 = s.Bs[(tc)*33 + k];
            float b1 = s.Bs[(tc + 16) * 33 + k];
            float b2 = s.Bs[(tc + 32) * 33 + k];
            float b3 = s.Bs[(tc + 48) * 33 + k];
            acc[0][0] += a0 * b0; acc[0][1] += a0 * b1; acc[0][2] += a0 * b2; acc[0][3] += a0 * b3;
            acc[1][0] += a1 * b0; acc[1][1] += a1 * b1; acc[1][2] += a1 * b2; acc[1][3] += a1 * b3;
            acc[2][0] += a2 * b0; acc[2][1] += a2 * b1; acc[2][2] += a2 * b2; acc[2][3] += a2 * b3;
            acc[3][0] += a3 * b0; acc[3][1] += a3 * b1; acc[3][2] += a3 * b2; acc[3][3] += a3 * b3;
        }
    }
#pragma unroll
    for (int i = 0; i < 4; i++)
#pragma unroll
        for (int j = 0; j < 4; j++)
            C[(size_t)(row0 + tr + 8 * i) * BB + col0 + tc + 16 * j] = acc[i][j];
    if (CT) {
#pragma unroll
        for (int i = 0; i < 4; i++)
#pragma unroll
            for (int j = 0; j < 4; j++)
                CT[(size_t)(col0 + tc + 16 * j) * BB + row0 + tr + 8 * i] = acc[i][j];
    }
}

// ============================================================================
// K1-half body: block (b, h) computes sim partial over K in [h*384,(h+1)*384)
// (4 warps x 96 k, 3 chunks each, pipelined). Writes d_simP[b][h] and the tlm
// slice for its k-range. NO handshake — phase barrier orders everything.
// ============================================================================
__device__ __forceinline__ void k1half_body(K1Sm& s, const float* __restrict__ VL,
                                            const float* __restrict__ TL,
                                            int b, int h) {
    int tid = threadIdx.x, w = tid >> 5, lane = tid & 31;
    int koff = h * 384 + w * 96;
    int tr = lane >> 3, tc = lane & 7;

    const float* VLb = VL + (size_t)b * 16 * DD;
    const float* TLb = TL + (size_t)b * 32 * DD;

    float acc[4][4] = {};
    float4 va[4], vb[8];

#pragma unroll
    for (int j = 0; j < 4; j++) {
        int idx = lane + 32 * j, row = idx >> 3, kq = idx & 7;
        va[j] = *(const float4*)(VLb + row * DD + koff + 4 * kq);
    }
#pragma unroll
    for (int j = 0; j < 8; j++) {
        int idx = lane + 32 * j, row = idx >> 3, kq = idx & 7;
        vb[j] = *(const float4*)(TLb + row * DD + koff + 4 * kq);
    }

    for (int ks = 0; ks < 96; ks += 32) {
#pragma unroll
        for (int j = 0; j < 4; j++) {
            int idx = lane + 32 * j, row = idx >> 3, kq = idx & 7;
            float* p = &s.As[w][row * 33 + 4 * kq];
            p[0] = va[j].x; p[1] = va[j].y; p[2] = va[j].z; p[3] = va[j].w;
        }
#pragma unroll
        for (int j = 0; j < 8; j++) {
            int idx = lane + 32 * j, row = idx >> 3, kq = idx & 7;
            float* p = &s.Bs[w][row * 33 + 4 * kq];
            p[0] = vb[j].x; p[1] = vb[j].y; p[2] = vb[j].z; p[3] = vb[j].w;
        }
        __syncwarp();
        if (ks + 32 < 96) {   // prefetch next chunk (hidden by compute)
#pragma unroll
            for (int j = 0; j < 4; j++) {
                int idx = lane + 32 * j, row = idx >> 3, kq = idx & 7;
                va[j] = *(const float4*)(VLb + row * DD + koff + ks + 32 + 4 * kq);
            }
#pragma unroll
            for (int j = 0; j < 8; j++) {
                int idx = lane + 32 * j, row = idx >> 3, kq = idx & 7;
                vb[j] = *(const float4*)(TLb + row * DD + koff + ks + 32 + 4 * kq);
            }
        }
#pragma unroll 16
        for (int k = 0; k < 32; k++) {
            float a0 = s.As[w][(tr)*33 + k];
            float a1 = s.As[w][(tr + 4) * 33 + k];
            float a2 = s.As[w][(tr + 8) * 33 + k];
            float a3 = s.As[w][(tr + 12) * 33 + k];
            float b0 = s.Bs[w][(tc)*33 + k];
            float b1 = s.Bs[w][(tc + 8) * 33 + k];
            float b2 = s.Bs[w][(tc + 16) * 33 + k];
            float b3 = s.Bs[w][(tc + 24) * 33 + k];
            acc[0][0] += a0 * b0; acc[0][1] += a0 * b1; acc[0][2] += a0 * b2; acc[0][3] += a0 * b3;
            acc[1][0] += a1 * b0; acc[1][1] += a1 * b1; acc[1][2] += a1 * b2; acc[1][3] += a1 * b3;
            acc[2][0] += a2 * b0; acc[2][1] += a2 * b1; acc[2][2] += a2 * b2; acc[2][3] += a2 * b3;
            acc[3][0] += a3 * b0; acc[3][1] += a3 * b1; acc[3][2] += a3 * b2; acc[3][3] += a3 * b3;
        }
        // tl_mean fold: lane = k column; sum the 32 s-rows (conflict-free)
        float tsum = 0.f;
#pragma unroll
        for (int s2 = 0; s2 < 32; s2++) tsum += s.Bs[w][s2 * 33 + lane];
        d_tlm[b * DD + koff + ks + lane] = tsum * (1.f / 32.f);
        __syncwarp();
    }
#pragma unroll
    for (int i = 0; i < 4; i++)
#pragma unroll
        for (int j = 0; j < 4; j++)
            s.simb[w][(tr + 4 * i) * 32 + tc + 8 * j] = acc[i][j];
    __syncthreads();

    // combine 4 warp k-partials -> block's half-partial -> global
#pragma unroll
    for (int r = 0; r < 4; r++) {
        int i = tid + 128 * r;
        d_simP[b][h][i] = s.simb[0][i] + s.simb[1][i] + s.simb[2][i] + s.simb[3][i];
    }
}

// ============================================================================
// Finalize body (phase B, one block per b): sims = P0 + P1 (fixed order),
// tw = softmax_t(scale*rowmax_s), vq[b] = sum_t tw[t]*VL[b,t] (VL hits L2).
// ============================================================================
__device__ __forceinline__ void finalize_body(K1Sm& s, const float* __restrict__ VL,
                                              const float* __restrict__ temp, int b) {
    int tid = threadIdx.x, lane = tid & 31;
    const float* VLb = VL + (size_t)b * 16 * DD;

#pragma unroll
    for (int r = 0; r < 4; r++) {
        int i = tid + 128 * r;
        s.sims[i] = d_simP[b][0][i] + d_simP[b][1][i];
    }
    __syncthreads();

    {   // row max over s: thread (t=tid>>3, g=tid&7)
        int t = tid >> 3, g = tid & 7;
        float m = s.sims[t * 32 + g];
#pragma unroll
        for (int u = 1; u < 4; u++) m = fmaxf(m, s.sims[t * 32 + g + 8 * u]);
#pragma unroll
        for (int off = 1; off < 8; off <<= 1)
            m = fmaxf(m, __shfl_xor_sync(0xffffffffu, m, off));
        if (g == 0) s.redm[t] = m;
    }
    __syncthreads();

    if (tid < 32) {
        float scale = expf(__ldg(temp));
        float v = (lane < 16) ? s.redm[lane] * scale : -CUDART_INF_F;
        float mx = v;
#pragma unroll
        for (int o = 16; o; o >>= 1) mx = fmaxf(mx, __shfl_xor_sync(0xffffffffu, mx, o));
        float e = (lane < 16) ? expf(v - mx) : 0.f;
        float ssum = e;
#pragma unroll
        for (int o = 16; o; o >>= 1) ssum += __shfl_xor_sync(0xffffffffu, ssum, o);
        if (lane < 16) s.tw[lane] = e / ssum;
    }
    __syncthreads();

#pragma unroll
    for (int r = 0; r < 6; r++) {
        int d = tid + 128 * r;
        float a = 0.f;
#pragma unroll
        for (int t2 = 0; t2 < 16; t2++) a += s.tw[t2] * __ldg(VLb + t2 * DD + d);
        d_vq[b * DD + d] = a;
    }
}

// ============================================================================
// LSE body: one warp handles row gw of {G rows, G cols (GTp), L rows}.
// ============================================================================
__device__ __forceinline__ void lse_warp(int gw, int lane, float scale) {
    int kind = gw >> 8, r = gw & 255;
    float4 x0 = make_float4(0.f, 0.f, 0.f, 0.f);
    float4 x1 = make_float4(0.f, 0.f, 0.f, 0.f);
    int np = (kind == 2) ? SPLITL : SPLITG;
    for (int p = 0; p < np; p++) {
        const float* src = (kind == 0 ? d_Gp[p] : kind == 1 ? d_GTp[p] : d_Lp[p]) + r * BB;
        float4 a = ((const float4*)src)[lane];
        float4 b2 = ((const float4*)src)[lane + 32];
        x0.x += a.x; x0.y += a.y; x0.z += a.z; x0.w += a.w;
        x1.x += b2.x; x1.y += b2.y; x1.z += b2.z; x1.w += b2.w;
    }
    x0.x *= scale; x0.y *= scale; x0.z *= scale; x0.w *= scale;
    x1.x *= scale; x1.y *= scale; x1.z *= scale; x1.w *= scale;

    {   // diagonal element (col == r)
        int f = r >> 2, e = r & 3;
        if (kind == 0 && f < 32 && lane == f) d_diagG[r] = sel4(x0, e);
        if (kind == 0 && f >= 32 && lane == f - 32) d_diagG[r] = sel4(x1, e);
        if (kind == 2 && f < 32 && lane == f) d_diagL[r] = sel4(x0, e);
        if (kind == 2 && f >= 32 && lane == f - 32) d_diagL[r] = sel4(x1, e);
    }

    float m = fmaxf(fmaxf(fmaxf(x0.x, x0.y), fmaxf(x0.z, x0.w)),
                    fmaxf(fmaxf(x1.x, x1.y), fmaxf(x1.z, x1.w)));
#pragma unroll
    for (int o = 16; o; o >>= 1) m = fmaxf(m, __shfl_xor_sync(0xffffffffu, m, o));
    float ss = expf(x0.x - m) + expf(x0.y - m) + expf(x0.z - m) + expf(x0.w - m)
             + expf(x1.x - m) + expf(x1.y - m) + expf(x1.z - m) + expf(x1.w - m);
#pragma unroll
    for (int o = 16; o; o >>= 1) ss += __shfl_xor_sync(0xffffffffu, ss, o);
    if (lane == 0) d_lse[gw] = m + logf(ss);
}

// ============================================================================
// MEGA KERNEL v2 — 640 blocks, single wave (launch_bounds forces 5 blocks/SM).
// Phase A: bx<512 -> k1-half (b=bx>>1, h=bx&1); bx in [512,640) -> G-gemm.
// Phase B: bx<256 -> softmax+vq finalize for b=bx.
// Phase C: bx in [256,640) -> L-gemm (32 tiles x 12 splits of K=64).
// Phase D: bx<192 -> 4 lse warps each; last finisher -> final combine + reset.
// Only blocks 0..191 ever WAIT on bar3; resets happen after all have passed.
// ============================================================================
__global__ void __launch_bounds__(128, 5) mega_kernel(const float* __restrict__ VL,
                                                      const float* __restrict__ TL,
                                                      const float* __restrict__ VG,
                                                      const float* __restrict__ TG,
                                                      const float* __restrict__ temp,
                                                      float* __restrict__ out) {
    __shared__ SmU sm;
    int bx = blockIdx.x;
    int tid = threadIdx.x;

    // ---- Phase A ----
    if (bx < 512) {
        k1half_body(sm.k1, VL, TL, bx >> 1, bx & 1);
    } else {
        int gi = bx - 512;          // 0..127
        int z = gi >> 5;            // split 0..3 (K=192 each)
        int tile = gi & 31;         // 8 row-tiles x 4 col-tiles
        int row0 = (tile >> 2) * 32, col0 = (tile & 3) * 64;
        gemm_body(sm.g, VG, TG, d_Gp[z], d_GTp[z], row0, col0, z * 192, 6);
    }

    bar_arrive(&d_bar1);
    bar_wait(&d_bar1, GRID);

    // ---- Phase B: finalize softmax + vq (256 blocks) ----
    if (bx < 256) finalize_body(sm.k1, VL, temp, bx);

    bar_arrive(&d_bar2);
    bar_wait(&d_bar2, GRID);

    // ---- Phase C: L = vq @ tlm^T (blocks 256..639: 32 tiles x 12 splits) ----
    if (bx >= 256) {
        int gi = bx - 256;          // 0..383
        int z = gi >> 5;            // 0..11 (K=64 each)
        int tile = gi & 31;
        int row0 = (tile >> 2) * 32, col0 = (tile & 3) * 64;
        gemm_body(sm.g, d_vq, d_tlm, d_Lp[z], nullptr, row0, col0, z * 64, 2);
    }

    bar_arrive(&d_bar3);
    if (bx >= 192) return;          // non-waiters exit (never poll bar3)
    bar_wait(&d_bar3, GRID);

    // ---- Phase D: LSE (768 rows over 192 blocks x 4 warps) ----
    {
        float scale = expf(__ldg(temp));
        int gw = bx * 4 + (tid >> 5);
        lse_warp(gw, tid & 31, scale);
    }

    // ---- final combine in last-finishing phase-D block ----
    __threadfence();
    __shared__ bool isLast;
    if (tid == 0) {
        unsigned int old = atomicAdd(&d_ctr, 1u);
        isLast = (old == 191u);
    }
    __syncthreads();
    if (!isLast) return;

    {
        float sg = 0.f, sl = 0.f;
#pragma unroll
        for (int r = 0; r < 2; r++) {
            int b = tid + 128 * r;
            float g = d_diagG[b];
            float l = d_diagL[b];
            sg += (d_lse[b] - g) + (d_lse[256 + b] - g);
            sl += d_lse[512 + b] - l;
        }
        __shared__ float s1[4], s2[4];
        int w2 = tid >> 5, l2 = tid & 31;
#pragma unroll
        for (int o = 16; o; o >>= 1) {
            sg += __shfl_xor_sync(0xffffffffu, sg, o);
            sl += __shfl_xor_sync(0xffffffffu, sl, o);
        }
        if (l2 == 0) { s1[w2] = sg; s2[w2] = sl; }
        __syncthreads();
        if (tid == 0) {
            float tg = s1[0] + s1[1] + s1[2] + s1[3];
            float tl2 = s2[0] + s2[1] + s2[2] + s2[3];
            out[0] = 0.3f * (tg / 256.f) + 0.4f * (tl2 / 256.f);
            // replay-safe reset: all barrier waiters have provably passed
            d_bar1 = 0;
            d_bar2 = 0;
            d_bar3 = 0;
            d_ctr = 0;
        }
    }
}

extern "C" void kernel_launch(void* const* d_in, const int* in_sizes, int n_in,
                              void* d_out, int out_size) {
    const float* vg   = (const float*)d_in[0];  // video_global [256,768]
    const float* tg   = (const float*)d_in[1];  // text_global  [256,768]
    const float* vl   = (const float*)d_in[2];  // video_local  [256,16,768]
    const float* tl   = (const float*)d_in[3];  // text_local   [256,32,768]
    const float* temp = (const float*)d_in[4];  // temp [1]
    float* out = (float*)d_out;

    mega_kernel<<<GRID, 128>>>(vl, tl, vg, tg, temp, out);
}

// round 15
// speedup vs baseline: 1.3292x; 1.3292x over previous
#include <cuda_runtime.h>
#include <math_constants.h>

#define BB 256
#define DD 768
#define SPLITG 4
#define SPLITL 8

// ---- scratch (static device globals; no allocation) ----
__device__ float d_vq[BB * DD];
__device__ float d_tlm[BB * DD];
__device__ float d_Gp[SPLITG][BB * BB];
__device__ float d_GTp[SPLITG][BB * BB];
__device__ float d_Lp[SPLITL][BB * BB];
__device__ float d_lse[3 * BB];
__device__ float d_diagG[BB];
__device__ float d_diagL[BB];
__device__ volatile unsigned int d_bar = 0;   // combo phase 1 -> 2
__device__ unsigned int d_ctr = 0;            // combo phase 2 completion

__device__ __forceinline__ float sel4(float4 v, int e) {
    return e == 0 ? v.x : e == 1 ? v.y : e == 2 ? v.z : v.w;
}

// ---- shared-memory views ----
struct K1Sm {
    float As[4][16 * 33];
    float Bs[4][32 * 33];
    float simb[4][512];
    float sims[512];
    float redm[16];
    float tw[16];
};
struct GemmSm {
    float As[32 * 33];   // A tile: 32 rows x 32 k, pitch 33
    float Bs[64 * 33];   // B tile: 64 rows x 32 k, pitch 33
};
union SmU { K1Sm k1; GemmSm g; };

// ============================================================================
// GEMM body (the proven R4/33.3us version): C = A @ B^T on a 32x64 tile,
// K-slice [kbase, kbase+32*nch). 128 threads; thread (tr=tid>>4, tc=tid&15)
// owns rows {tr+8i}, cols {tc+16j}. Pitch-33 conflict-free smem.
// ============================================================================
__device__ __forceinline__ void gemm_body(GemmSm& s, const float* __restrict__ A,
                                          const float* __restrict__ Bm,
                                          float* __restrict__ C, float* __restrict__ CT,
                                          int row0, int col0, int kbase, int nch) {
    int tid = threadIdx.x;
    int tr = tid >> 4, tc = tid & 15;
    float acc[4][4] = {};

    for (int ch = 0; ch < nch; ch++) {
        int kb = kbase + ch * 32;
        float4 va[2], vb[4];
#pragma unroll
        for (int j = 0; j < 2; j++) {
            int idx = tid + 128 * j, row = idx >> 3, kq = idx & 7;
            va[j] = *(const float4*)(A + (size_t)(row0 + row) * DD + kb + 4 * kq);
        }
#pragma unroll
        for (int j = 0; j < 4; j++) {
            int idx = tid + 128 * j, row = idx >> 3, kq = idx & 7;
            vb[j] = *(const float4*)(Bm + (size_t)(col0 + row) * DD + kb + 4 * kq);
        }
        __syncthreads();  // previous chunk's compute done before overwrite
#pragma unroll
        for (int j = 0; j < 2; j++) {
            int idx = tid + 128 * j, row = idx >> 3, kq = idx & 7;
            float* p = &s.As[row * 33 + 4 * kq];
            p[0] = va[j].x; p[1] = va[j].y; p[2] = va[j].z; p[3] = va[j].w;
        }
#pragma unroll
        for (int j = 0; j < 4; j++) {
            int idx = tid + 128 * j, row = idx >> 3, kq = idx & 7;
            float* p = &s.Bs[row * 33 + 4 * kq];
            p[0] = vb[j].x; p[1] = vb[j].y; p[2] = vb[j].z; p[3] = vb[j].w;
        }
        __syncthreads();
#pragma unroll 16
        for (int k = 0; k < 32; k++) {
            float a0 = s.As[(tr)*33 + k];
            float a1 = s.As[(tr + 8) * 33 + k];
            float a2 = s.As[(tr + 16) * 33 + k];
            float a3 = s.As[(tr + 24) * 33 + k];
            float b0 = s.Bs[(tc)*33 + k];
            float b1 = s.Bs[(tc + 16) * 33 + k];
            float b2 = s.Bs[(tc + 32) * 33 + k];
            float b3 = s.Bs[(tc + 48) * 33 + k];
            acc[0][0] += a0 * b0; acc[0][1] += a0 * b1; acc[0][2] += a0 * b2; acc[0][3] += a0 * b3;
            acc[1][0] += a1 * b0; acc[1][1] += a1 * b1; acc[1][2] += a1 * b2; acc[1][3] += a1 * b3;
            acc[2][0] += a2 * b0; acc[2][1] += a2 * b1; acc[2][2] += a2 * b2; acc[2][3] += a2 * b3;
            acc[3][0] += a3 * b0; acc[3][1] += a3 * b1; acc[3][2] += a3 * b2; acc[3][3] += a3 * b3;
        }
    }
#pragma unroll
    for (int i = 0; i < 4; i++)
#pragma unroll
        for (int j = 0; j < 4; j++)
            C[(size_t)(row0 + tr + 8 * i) * BB + col0 + tc + 16 * j] = acc[i][j];
    if (CT) {
#pragma unroll
        for (int i = 0; i < 4; i++)
#pragma unroll
            for (int j = 0; j < 4; j++)
                CT[(size_t)(col0 + tc + 16 * j) * BB + row0 + tr + 8 * i] = acc[i][j];
    }
}

// ============================================================================
// K1 body (proven R2/R4 version): per b, sim[16][32] = VL_b @ TL_b^T
// (4 warps split K, 192 each), tw = softmax_t(scale*rowmax_s),
// vq[b] = sum_t tw[t]*VL[b,t], tlm[b] = mean_s TL[b,s] folded into staging.
// ============================================================================
__device__ __forceinline__ void k1_body(K1Sm& s, const float* __restrict__ VL,
                                        const float* __restrict__ TL,
                                        const float* __restrict__ temp, int b) {
    int tid = threadIdx.x, w = tid >> 5, lane = tid & 31;
    int koff = w * 192;
    int tr = lane >> 3, tc = lane & 7;

    const float* VLb = VL + (size_t)b * 16 * DD;
    const float* TLb = TL + (size_t)b * 32 * DD;

    float acc[4][4] = {};

    for (int ks = 0; ks < 192; ks += 32) {
#pragma unroll
        for (int j = 0; j < 4; j++) {
            int idx = lane + 32 * j, row = idx >> 3, kq = idx & 7;
            float4 v = *(const float4*)(VLb + row * DD + koff + ks + 4 * kq);
            float* p = &s.As[w][row * 33 + 4 * kq];
            p[0] = v.x; p[1] = v.y; p[2] = v.z; p[3] = v.w;
        }
#pragma unroll
        for (int j = 0; j < 8; j++) {
            int idx = lane + 32 * j, row = idx >> 3, kq = idx & 7;
            float4 v = *(const float4*)(TLb + row * DD + koff + ks + 4 * kq);
            float* p = &s.Bs[w][row * 33 + 4 * kq];
            p[0] = v.x; p[1] = v.y; p[2] = v.z; p[3] = v.w;
        }
        __syncwarp();
#pragma unroll 16
        for (int k = 0; k < 32; k++) {
            float a0 = s.As[w][(tr)*33 + k];
            float a1 = s.As[w][(tr + 4) * 33 + k];
            float a2 = s.As[w][(tr + 8) * 33 + k];
            float a3 = s.As[w][(tr + 12) * 33 + k];
            float b0 = s.Bs[w][(tc)*33 + k];
            float b1 = s.Bs[w][(tc + 8) * 33 + k];
            float b2 = s.Bs[w][(tc + 16) * 33 + k];
            float b3 = s.Bs[w][(tc + 24) * 33 + k];
            acc[0][0] += a0 * b0; acc[0][1] += a0 * b1; acc[0][2] += a0 * b2; acc[0][3] += a0 * b3;
            acc[1][0] += a1 * b0; acc[1][1] += a1 * b1; acc[1][2] += a1 * b2; acc[1][3] += a1 * b3;
            acc[2][0] += a2 * b0; acc[2][1] += a2 * b1; acc[2][2] += a2 * b2; acc[2][3] += a2 * b3;
            acc[3][0] += a3 * b0; acc[3][1] += a3 * b1; acc[3][2] += a3 * b2; acc[3][3] += a3 * b3;
        }
        // tl_mean fold: lane = k column; sum the 32 s-rows (conflict-free)
        float tsum = 0.f;
#pragma unroll
        for (int s2 = 0; s2 < 32; s2++) tsum += s.Bs[w][s2 * 33 + lane];
        d_tlm[b * DD + koff + ks + lane] = tsum * (1.f / 32.f);
        __syncwarp();
    }
#pragma unroll
    for (int i = 0; i < 4; i++)
#pragma unroll
        for (int j = 0; j < 4; j++)
            s.simb[w][(tr + 4 * i) * 32 + tc + 8 * j] = acc[i][j];
    __syncthreads();

#pragma unroll
    for (int r = 0; r < 4; r++) {
        int i = tid + 128 * r;
        s.sims[i] = s.simb[0][i] + s.simb[1][i] + s.simb[2][i] + s.simb[3][i];
    }
    __syncthreads();

    {   // row max over s
        int t = tid >> 3, g = tid & 7;
        float m = s.sims[t * 32 + g];
#pragma unroll
        for (int u = 1; u < 4; u++) m = fmaxf(m, s.sims[t * 32 + g + 8 * u]);
#pragma unroll
        for (int off = 1; off < 8; off <<= 1)
            m = fmaxf(m, __shfl_xor_sync(0xffffffffu, m, off));
        if (g == 0) s.redm[t] = m;
    }
    __syncthreads();

    if (tid < 32) {
        float scale = expf(__ldg(temp));
        float v = (lane < 16) ? s.redm[lane] * scale : -CUDART_INF_F;
        float mx = v;
#pragma unroll
        for (int o = 16; o; o >>= 1) mx = fmaxf(mx, __shfl_xor_sync(0xffffffffu, mx, o));
        float e = (lane < 16) ? expf(v - mx) : 0.f;
        float ssum = e;
#pragma unroll
        for (int o = 16; o; o >>= 1) ssum += __shfl_xor_sync(0xffffffffu, ssum, o);
        if (lane < 16) s.tw[lane] = e / ssum;
    }
    __syncthreads();

#pragma unroll
    for (int r = 0; r < 6; r++) {
        int d = tid + 128 * r;
        float a = 0.f;
#pragma unroll
        for (int t2 = 0; t2 < 16; t2++) a += s.tw[t2] * __ldg(VLb + t2 * DD + d);
        d_vq[b * DD + d] = a;
    }
}

// ============================================================================
// LSE body: one warp handles row gw of {G rows, G cols (GTp), L rows}.
// ============================================================================
__device__ __forceinline__ void lse_warp(int gw, int lane, float scale) {
    int kind = gw >> 8, r = gw & 255;
    float4 x0 = make_float4(0.f, 0.f, 0.f, 0.f);
    float4 x1 = make_float4(0.f, 0.f, 0.f, 0.f);
    int np = (kind == 2) ? SPLITL : SPLITG;
    for (int p = 0; p < np; p++) {
        const float* src = (kind == 0 ? d_Gp[p] : kind == 1 ? d_GTp[p] : d_Lp[p]) + r * BB;
        float4 a = ((const float4*)src)[lane];
        float4 b2 = ((const float4*)src)[lane + 32];
        x0.x += a.x; x0.y += a.y; x0.z += a.z; x0.w += a.w;
        x1.x += b2.x; x1.y += b2.y; x1.z += b2.z; x1.w += b2.w;
    }
    x0.x *= scale; x0.y *= scale; x0.z *= scale; x0.w *= scale;
    x1.x *= scale; x1.y *= scale; x1.z *= scale; x1.w *= scale;

    {   // diagonal element (col == r)
        int f = r >> 2, e = r & 3;
        if (kind == 0 && f < 32 && lane == f) d_diagG[r] = sel4(x0, e);
        if (kind == 0 && f >= 32 && lane == f - 32) d_diagG[r] = sel4(x1, e);
        if (kind == 2 && f < 32 && lane == f) d_diagL[r] = sel4(x0, e);
        if (kind == 2 && f >= 32 && lane == f - 32) d_diagL[r] = sel4(x1, e);
    }

    float m = fmaxf(fmaxf(fmaxf(x0.x, x0.y), fmaxf(x0.z, x0.w)),
                    fmaxf(fmaxf(x1.x, x1.y), fmaxf(x1.z, x1.w)));
#pragma unroll
    for (int o = 16; o; o >>= 1) m = fmaxf(m, __shfl_xor_sync(0xffffffffu, m, o));
    float ss = expf(x0.x - m) + expf(x0.y - m) + expf(x0.z - m) + expf(x0.w - m)
             + expf(x1.x - m) + expf(x1.y - m) + expf(x1.z - m) + expf(x1.w - m);
#pragma unroll
    for (int o = 16; o; o >>= 1) ss += __shfl_xor_sync(0xffffffffu, ss, o);
    if (lane == 0) d_lse[gw] = m + logf(ss);
}

// ============================================================================
// Launch 1 (PROVEN 33.3us structure, unchanged): blocks [0,256) = k1;
// blocks [256,384) = G-gemm (32 tiles of 32x64 x 4 k-splits of 192).
// ============================================================================
__global__ void __launch_bounds__(128) fused_kernel(const float* __restrict__ VL,
                                                    const float* __restrict__ TL,
                                                    const float* __restrict__ VG,
                                                    const float* __restrict__ TG,
                                                    const float* __restrict__ temp) {
    __shared__ SmU sm;
    int bx = blockIdx.x;
    if (bx < 256) {
        k1_body(sm.k1, VL, TL, temp, bx);
    } else {
        int gi = bx - 256;          // 0..127
        int z = gi >> 5;            // split 0..3 (K=192 each)
        int tile = gi & 31;         // 8 row-tiles x 4 col-tiles
        int row0 = (tile >> 2) * 32, col0 = (tile & 3) * 64;
        gemm_body(sm.g, VG, TG, d_Gp[z], d_GTp[z], row0, col0, z * 192, 6);
    }
}

// ============================================================================
// Launch 2 (NEW combo): phase 1 runs L-gemm (blocks 0..255: 32 tiles x 8
// splits of K=96) CONCURRENTLY with G-LSE (blocks 256..383: 512 G rows/cols,
// whose inputs completed at the launch boundary). One 384-block barrier
// (single-wave: 128 thr, ~13KB smem, <=96 regs -> >=5 blocks/SM, cap 740).
// Phase 2: blocks 0..63 do L-LSE (256 rows); last finisher combines + resets.
// ============================================================================
__global__ void __launch_bounds__(128) combo_kernel(const float* __restrict__ temp,
                                                    float* __restrict__ out) {
    __shared__ GemmSm sm;
    int bx = blockIdx.x;
    int tid = threadIdx.x;
    float scale = expf(__ldg(temp));

    // ---- Phase 1 ----
    if (bx < 256) {
        int z = bx >> 5;            // 0..7 (K=96 each)
        int tile = bx & 31;
        int row0 = (tile >> 2) * 32, col0 = (tile & 3) * 64;
        gemm_body(sm, d_vq, d_tlm, d_Lp[z], nullptr, row0, col0, z * 96, 3);
    } else {
        int gw = (bx - 256) * 4 + (tid >> 5);   // 0..511: G rows + G cols
        lse_warp(gw, tid & 31, scale);
    }

    // ---- barrier: arrive all; only blocks 0..63 wait ----
    __threadfence();
    __syncthreads();
    if (tid == 0) atomicAdd((unsigned int*)&d_bar, 1u);
    if (bx >= 64) return;           // non-waiters exit (never poll)
    if (tid == 0) {
        while (d_bar < 384u) __nanosleep(64);
    }
    __syncthreads();
    __threadfence();

    // ---- Phase 2: L-LSE (256 rows over 64 blocks x 4 warps) ----
    lse_warp(512 + bx * 4 + (tid >> 5), tid & 31, scale);

    // ---- final combine in last-finishing phase-2 block ----
    __threadfence();
    __shared__ bool isLast;
    if (tid == 0) {
        unsigned int old = atomicAdd(&d_ctr, 1u);
        isLast = (old == 63u);
    }
    __syncthreads();
    if (!isLast) return;

    {
        float sg = 0.f, sl = 0.f;
#pragma unroll
        for (int r = 0; r < 2; r++) {
            int b = tid + 128 * r;
            float g = d_diagG[b];
            float l = d_diagL[b];
            sg += (d_lse[b] - g) + (d_lse[256 + b] - g);
            sl += d_lse[512 + b] - l;
        }
        __shared__ float s1[4], s2[4];
        int w2 = tid >> 5, l2 = tid & 31;
#pragma unroll
        for (int o = 16; o; o >>= 1) {
            sg += __shfl_xor_sync(0xffffffffu, sg, o);
            sl += __shfl_xor_sync(0xffffffffu, sl, o);
        }
        if (l2 == 0) { s1[w2] = sg; s2[w2] = sl; }
        __syncthreads();
        if (tid == 0) {
            float tg = s1[0] + s1[1] + s1[2] + s1[3];
            float tl2 = s2[0] + s2[1] + s2[2] + s2[3];
            out[0] = 0.3f * (tg / 256.f) + 0.4f * (tl2 / 256.f);
            // replay-safe reset: all waiters (blocks 0..63) have passed
            d_bar = 0;
            d_ctr = 0;
        }
    }
}

extern "C" void kernel_launch(void* const* d_in, const int* in_sizes, int n_in,
                              void* d_out, int out_size) {
    const float* vg   = (const float*)d_in[0];  // video_global [256,768]
    const float* tg   = (const float*)d_in[1];  // text_global  [256,768]
    const float* vl   = (const float*)d_in[2];  // video_local  [256,16,768]
    const float* tl   = (const float*)d_in[3];  // text_local   [256,32,768]
    const float* temp = (const float*)d_in[4];  // temp [1]
    float* out = (float*)d_out;

    fused_kernel<<<384, 128>>>(vl, tl, vg, tg, temp);
    combo_kernel<<<384, 128>>>(temp, out);
}